// round 2
// baseline (speedup 1.0000x reference)
#include <cuda_runtime.h>

#define B_PTS   131072
#define HDIM    256
#define NBLK    8
#define NMID    3
#define MT      32          // points per CTA
#define NTHREADS 256
#define SROW    260         // padded row stride of state matrix (floats)
#define KC      32          // K tile

// shared memory layout (float offsets)
#define OFF_S    0                       // 96 rows (h:0-31, t0:32-63, t1:64-95) x SROW
#define OFF_WT   (96*SROW)               // 32 x 256 weight tile
#define OFF_WOS  (OFF_WT + KC*HDIM)      // 512: staged Wo
#define OFF_ZX   (OFF_WOS + 512)         // 64
#define OFF_VV   (OFF_ZX + 64)           // 64
#define OFF_DL   (OFF_VV + 64)           // 32
#define OFF_RED  (OFF_DL + 32)           // 192 reduction slots
#define SMEM_FLOATS (OFF_RED + 192)
#define SMEM_BYTES  (SMEM_FLOATS * 4)

// packed dual-FMA: d = a*b + d  (sm_100a/sm_103a f32x2 pipe, 2x FFMA throughput)
__device__ __forceinline__ void ffma2(float2 &d, const float2 &a, const float2 &b) {
    asm("fma.rn.f32x2 %0, %1, %2, %0;"
        : "+l"(reinterpret_cast<unsigned long long &>(d))
        : "l"(reinterpret_cast<const unsigned long long &>(a)),
          "l"(reinterpret_cast<const unsigned long long &>(b)));
}

__global__ void __launch_bounds__(NTHREADS, 1)
eq_resflow_kernel(const float *__restrict__ x,  const float *__restrict__ v,
                  const float *__restrict__ Wi, const float *__restrict__ bi,
                  const float *__restrict__ Wm, const float *__restrict__ bm,
                  const float *__restrict__ Wo, const float *__restrict__ bo,
                  float *__restrict__ out)
{
    extern __shared__ float sm[];
    float *S   = sm + OFF_S;
    float *Wt  = sm + OFF_WT;
    float *Wos = sm + OFF_WOS;
    float *zx  = sm + OFF_ZX;
    float *vv  = sm + OFF_VV;
    float *dl  = sm + OFF_DL;
    float *red = sm + OFF_RED;

    const int tid = threadIdx.x;
    const int tx  = tid & 15;      // column group (16)
    const int ty  = tid >> 4;      // point group  (16) -> 2 points each
    const int pbase = blockIdx.x * MT;

    if (tid < MT) {
        float2 xx = *reinterpret_cast<const float2 *>(x + 2 * (pbase + tid));
        float2 vx = *reinterpret_cast<const float2 *>(v + 2 * (pbase + tid));
        zx[2 * tid] = xx.x;  zx[2 * tid + 1] = xx.y;
        vv[2 * tid] = vx.x;  vv[2 * tid + 1] = vx.y;
        dl[tid] = 0.f;
    }
    __syncthreads();

    for (int b = 0; b < NBLK; ++b) {
        // ---------------- layer 0 : 2 -> 256 (primal + both tangent columns)
        {
            const float *Wi0 = Wi + (size_t)(b * 2 + 0) * HDIM;
            const float *Wi1 = Wi + (size_t)(b * 2 + 1) * HDIM;
            const float *bib = bi + (size_t)b * HDIM;
            #pragma unroll
            for (int pi = 0; pi < 2; ++pi) {
                int p = 2 * ty + pi;
                float x0 = zx[2 * p], x1 = zx[2 * p + 1];
                #pragma unroll
                for (int j = 0; j < 8; ++j) {
                    int n = tx * 2 + j * 32;
                    float2 w0 = *reinterpret_cast<const float2 *>(Wi0 + n);
                    float2 w1 = *reinterpret_cast<const float2 *>(Wi1 + n);
                    float2 bb = *reinterpret_cast<const float2 *>(bib + n);
                    float px = fmaf(x0, w0.x, fmaf(x1, w1.x, bb.x));
                    float py = fmaf(x0, w0.y, fmaf(x1, w1.y, bb.y));
                    float mx = px > 0.f ? 1.f : 0.f;
                    float my = py > 0.f ? 1.f : 0.f;
                    float *Sh = S + (0 * MT + p) * SROW + n;
                    float *S0 = S + (1 * MT + p) * SROW + n;
                    float *S1 = S + (2 * MT + p) * SROW + n;
                    Sh[0] = fmaxf(px, 0.f); Sh[1] = fmaxf(py, 0.f);
                    S0[0] = w0.x * mx;      S0[1] = w0.y * my;   // tangent e0
                    S1[0] = w1.x * mx;      S1[1] = w1.y * my;   // tangent e1
                }
            }
        }

        // ---------------- 3 mid layers : 256 -> 256, fused GEMM over 3 states
        for (int lj = 0; lj < NMID; ++lj) {
            const float *W    = Wm + (size_t)(b * NMID + lj) * HDIM * HDIM;
            const float *bias = bm + (size_t)(b * NMID + lj) * HDIM;

            float2 acc[2][3][8];
            #pragma unroll
            for (int pi = 0; pi < 2; ++pi)
                #pragma unroll
                for (int s = 0; s < 3; ++s)
                    #pragma unroll
                    for (int j = 0; j < 8; ++j)
                        acc[pi][s][j] = make_float2(0.f, 0.f);

            for (int st = 0; st < HDIM / KC; ++st) {
                __syncthreads();  // prior stage reads done / prior epilogue visible
                {
                    const float4 *Wg = reinterpret_cast<const float4 *>(W + (size_t)st * KC * HDIM);
                    float4 *Wt4 = reinterpret_cast<float4 *>(Wt);
                    #pragma unroll
                    for (int i = 0; i < 8; ++i) {
                        int idx = tid + i * NTHREADS;   // 2048 float4 = 32x256 floats
                        Wt4[idx] = Wg[idx];
                    }
                }
                __syncthreads();

                const int k0 = st * KC;
                #pragma unroll 4
                for (int k = 0; k < KC; ++k) {
                    float2 a2[2][3];
                    #pragma unroll
                    for (int pi = 0; pi < 2; ++pi) {
                        int p = 2 * ty + pi;
                        #pragma unroll
                        for (int s = 0; s < 3; ++s) {
                            float av = S[(s * MT + p) * SROW + k0 + k];
                            a2[pi][s] = make_float2(av, av);
                        }
                    }
                    float2 wf[8];
                    #pragma unroll
                    for (int j = 0; j < 8; ++j)
                        wf[j] = *reinterpret_cast<const float2 *>(Wt + k * HDIM + tx * 2 + j * 32);
                    #pragma unroll
                    for (int pi = 0; pi < 2; ++pi)
                        #pragma unroll
                        for (int s = 0; s < 3; ++s)
                            #pragma unroll
                            for (int j = 0; j < 8; ++j)
                                ffma2(acc[pi][s][j], a2[pi][s], wf[j]);
                }
            }
            __syncthreads();   // all GEMM reads of S complete before overwrite

            // epilogue: relu on primal, mask tangents, write back
            #pragma unroll
            for (int pi = 0; pi < 2; ++pi) {
                int p = 2 * ty + pi;
                #pragma unroll
                for (int j = 0; j < 8; ++j) {
                    int n = tx * 2 + j * 32;
                    float2 bb = *reinterpret_cast<const float2 *>(bias + n);
                    float px = acc[pi][0][j].x + bb.x;
                    float py = acc[pi][0][j].y + bb.y;
                    float mx = px > 0.f ? 1.f : 0.f;
                    float my = py > 0.f ? 1.f : 0.f;
                    float *Sh = S + (0 * MT + p) * SROW + n;
                    float *S0 = S + (1 * MT + p) * SROW + n;
                    float *S1 = S + (2 * MT + p) * SROW + n;
                    Sh[0] = fmaxf(px, 0.f);       Sh[1] = fmaxf(py, 0.f);
                    S0[0] = acc[pi][1][j].x * mx; S0[1] = acc[pi][1][j].y * my;
                    S1[0] = acc[pi][2][j].x * mx; S1[1] = acc[pi][2][j].y * my;
                }
            }
            __syncthreads();
        }

        // ---------------- output layer : 256 -> 2, Jacobian + power series
        {
            const float4 *Wog = reinterpret_cast<const float4 *>(Wo + (size_t)b * HDIM * 2);
            float4 *Wos4 = reinterpret_cast<float4 *>(Wos);
            if (tid < 128) Wos4[tid] = Wog[tid];
        }
        __syncthreads();

        if (tid < 192) {     // 32 points x 3 states x 2 output cols
            int p   = tid & 31;
            int idx = tid >> 5;          // 0..5 = s*2 + c
            int s = idx >> 1, c = idx & 1;
            const float *Sr = S + (s * MT + p) * SROW;
            float sum = 0.f;
            #pragma unroll 8
            for (int k = 0; k < HDIM; ++k)
                sum = fmaf(Sr[k], Wos[2 * k + c], sum);
            red[idx * 32 + p] = sum;
        }
        __syncthreads();

        if (tid < MT) {
            int p = tid;
            float bo0 = __ldg(bo + b * 2 + 0);
            float bo1 = __ldg(bo + b * 2 + 1);
            float pre0 = red[0 * 32 + p] + bo0;     // primal out col 0
            float pre1 = red[1 * 32 + p] + bo1;     // primal out col 1
            float m0 = pre0 > 0.f ? 1.f : 0.f;
            float m1 = pre1 > 0.f ? 1.f : 0.f;
            // J[out][in]; s=1 <-> input dir 0, s=2 <-> input dir 1
            float J00 = red[2 * 32 + p] * m0;   // (s=1,c=0)
            float J10 = red[3 * 32 + p] * m1;   // (s=1,c=1)
            float J01 = red[4 * 32 + p] * m0;   // (s=2,c=0)
            float J11 = red[5 * 32 + p] * m1;   // (s=2,c=1)

            float v0 = vv[2 * p], v1 = vv[2 * p + 1];
            float w0 = v0, w1 = v1;
            float ldet = 0.f;
            const float coefs[5] = {1.f, -0.5f, 1.f / 3.f, -0.25f, 0.2f};
            #pragma unroll
            for (int k = 0; k < 5; ++k) {
                float nw0 = fmaf(J00, w0, J01 * w1);
                float nw1 = fmaf(J10, w0, J11 * w1);
                w0 = nw0; w1 = nw1;
                ldet = fmaf(coefs[k], fmaf(w0, v0, w1 * v1), ldet);
            }
            dl[p] -= ldet;
            zx[2 * p]     += fmaxf(pre0, 0.f);   // z = z + g(z)
            zx[2 * p + 1] += fmaxf(pre1, 0.f);
        }
        __syncthreads();
    }

    if (tid < MT) {
        int g = pbase + tid;
        out[2 * g]     = zx[2 * tid];
        out[2 * g + 1] = zx[2 * tid + 1];
        out[2 * B_PTS + g] = dl[tid];
    }
}

extern "C" void kernel_launch(void *const *d_in, const int *in_sizes, int n_in,
                              void *d_out, int out_size)
{
    const float *x  = (const float *)d_in[0];
    const float *v  = (const float *)d_in[1];
    const float *Wi = (const float *)d_in[2];
    const float *bi = (const float *)d_in[3];
    const float *Wm = (const float *)d_in[4];
    const float *bm = (const float *)d_in[5];
    const float *Wo = (const float *)d_in[6];
    const float *bo = (const float *)d_in[7];
    float *out = (float *)d_out;

    cudaFuncSetAttribute(eq_resflow_kernel,
                         cudaFuncAttributeMaxDynamicSharedMemorySize, SMEM_BYTES);
    eq_resflow_kernel<<<B_PTS / MT, NTHREADS, SMEM_BYTES>>>(x, v, Wi, bi, Wm, bm, Wo, bo, out);
}

// round 3
// speedup vs baseline: 1.0019x; 1.0019x over previous
#include <cuda_runtime.h>

#define B_PTS   131072
#define HDIM    256
#define NBLK    8
#define NMID    3
#define MT      32          // points per CTA
#define NTHREADS 256
#define SROW    260         // padded row stride of state matrix (floats)
#define KC      32          // K tile

// shared memory layout (float offsets)
#define OFF_S    0                       // 96 rows (h:0-31, t0:32-63, t1:64-95) x SROW
#define OFF_WT   (96*SROW)               // 32 x 256 weight tile
#define OFF_WOS  (OFF_WT + KC*HDIM)      // 512: staged Wo
#define OFF_ZX   (OFF_WOS + 512)         // 64
#define OFF_VV   (OFF_ZX + 64)           // 64
#define OFF_DL   (OFF_VV + 64)           // 32
#define OFF_RED  (OFF_DL + 32)           // 192 reduction slots
#define SMEM_FLOATS (OFF_RED + 192)
#define SMEM_BYTES  (SMEM_FLOATS * 4)

// packed dual-FMA: d = a*b + d  (sm_100a/sm_103a f32x2 pipe, 2x FFMA throughput)
__device__ __forceinline__ void ffma2(float2 &d, const float2 &a, const float2 &b) {
    asm("fma.rn.f32x2 %0, %1, %2, %0;"
        : "+l"(reinterpret_cast<unsigned long long &>(d))
        : "l"(reinterpret_cast<const unsigned long long &>(a)),
          "l"(reinterpret_cast<const unsigned long long &>(b)));
}

__global__ void __launch_bounds__(NTHREADS, 1)
eq_resflow_kernel(const float *__restrict__ x,  const float *__restrict__ v,
                  const float *__restrict__ Wi, const float *__restrict__ bi,
                  const float *__restrict__ Wm, const float *__restrict__ bm,
                  const float *__restrict__ Wo, const float *__restrict__ bo,
                  float *__restrict__ out)
{
    extern __shared__ float sm[];
    float *S   = sm + OFF_S;
    float *Wt  = sm + OFF_WT;
    float *Wos = sm + OFF_WOS;
    float *zx  = sm + OFF_ZX;
    float *vv  = sm + OFF_VV;
    float *dl  = sm + OFF_DL;
    float *red = sm + OFF_RED;

    const int tid = threadIdx.x;
    const int tx  = tid & 15;      // column group (16)
    const int ty  = tid >> 4;      // point group  (16) -> 2 points each
    const int pbase = blockIdx.x * MT;

    if (tid < MT) {
        float2 xx = *reinterpret_cast<const float2 *>(x + 2 * (pbase + tid));
        float2 vx = *reinterpret_cast<const float2 *>(v + 2 * (pbase + tid));
        zx[2 * tid] = xx.x;  zx[2 * tid + 1] = xx.y;
        vv[2 * tid] = vx.x;  vv[2 * tid + 1] = vx.y;
        dl[tid] = 0.f;
    }
    __syncthreads();

    for (int b = 0; b < NBLK; ++b) {
        // ---------------- layer 0 : 2 -> 256 (primal + both tangent columns)
        {
            const float *Wi0 = Wi + (size_t)(b * 2 + 0) * HDIM;
            const float *Wi1 = Wi + (size_t)(b * 2 + 1) * HDIM;
            const float *bib = bi + (size_t)b * HDIM;
            #pragma unroll
            for (int pi = 0; pi < 2; ++pi) {
                int p = 2 * ty + pi;
                float x0 = zx[2 * p], x1 = zx[2 * p + 1];
                #pragma unroll
                for (int j = 0; j < 8; ++j) {
                    int n = tx * 2 + j * 32;
                    float2 w0 = *reinterpret_cast<const float2 *>(Wi0 + n);
                    float2 w1 = *reinterpret_cast<const float2 *>(Wi1 + n);
                    float2 bb = *reinterpret_cast<const float2 *>(bib + n);
                    float px = fmaf(x0, w0.x, fmaf(x1, w1.x, bb.x));
                    float py = fmaf(x0, w0.y, fmaf(x1, w1.y, bb.y));
                    float mx = px > 0.f ? 1.f : 0.f;
                    float my = py > 0.f ? 1.f : 0.f;
                    float *Sh = S + (0 * MT + p) * SROW + n;
                    float *S0 = S + (1 * MT + p) * SROW + n;
                    float *S1 = S + (2 * MT + p) * SROW + n;
                    Sh[0] = fmaxf(px, 0.f); Sh[1] = fmaxf(py, 0.f);
                    S0[0] = w0.x * mx;      S0[1] = w0.y * my;   // tangent e0
                    S1[0] = w1.x * mx;      S1[1] = w1.y * my;   // tangent e1
                }
            }
        }

        // ---------------- 3 mid layers : 256 -> 256, fused GEMM over 3 states
        for (int lj = 0; lj < NMID; ++lj) {
            const float *W    = Wm + (size_t)(b * NMID + lj) * HDIM * HDIM;
            const float *bias = bm + (size_t)(b * NMID + lj) * HDIM;

            float2 acc[2][3][8];
            #pragma unroll
            for (int pi = 0; pi < 2; ++pi)
                #pragma unroll
                for (int s = 0; s < 3; ++s)
                    #pragma unroll
                    for (int j = 0; j < 8; ++j)
                        acc[pi][s][j] = make_float2(0.f, 0.f);

            for (int st = 0; st < HDIM / KC; ++st) {
                __syncthreads();  // prior stage reads done / prior epilogue visible
                {
                    const float4 *Wg = reinterpret_cast<const float4 *>(W + (size_t)st * KC * HDIM);
                    float4 *Wt4 = reinterpret_cast<float4 *>(Wt);
                    #pragma unroll
                    for (int i = 0; i < 8; ++i) {
                        int idx = tid + i * NTHREADS;   // 2048 float4 = 32x256 floats
                        Wt4[idx] = Wg[idx];
                    }
                }
                __syncthreads();

                const int k0 = st * KC;
                #pragma unroll 4
                for (int k = 0; k < KC; ++k) {
                    float2 a2[2][3];
                    #pragma unroll
                    for (int pi = 0; pi < 2; ++pi) {
                        int p = 2 * ty + pi;
                        #pragma unroll
                        for (int s = 0; s < 3; ++s) {
                            float av = S[(s * MT + p) * SROW + k0 + k];
                            a2[pi][s] = make_float2(av, av);
                        }
                    }
                    float2 wf[8];
                    #pragma unroll
                    for (int j = 0; j < 8; ++j)
                        wf[j] = *reinterpret_cast<const float2 *>(Wt + k * HDIM + tx * 2 + j * 32);
                    #pragma unroll
                    for (int pi = 0; pi < 2; ++pi)
                        #pragma unroll
                        for (int s = 0; s < 3; ++s)
                            #pragma unroll
                            for (int j = 0; j < 8; ++j)
                                ffma2(acc[pi][s][j], a2[pi][s], wf[j]);
                }
            }
            __syncthreads();   // all GEMM reads of S complete before overwrite

            // epilogue: relu on primal, mask tangents, write back
            #pragma unroll
            for (int pi = 0; pi < 2; ++pi) {
                int p = 2 * ty + pi;
                #pragma unroll
                for (int j = 0; j < 8; ++j) {
                    int n = tx * 2 + j * 32;
                    float2 bb = *reinterpret_cast<const float2 *>(bias + n);
                    float px = acc[pi][0][j].x + bb.x;
                    float py = acc[pi][0][j].y + bb.y;
                    float mx = px > 0.f ? 1.f : 0.f;
                    float my = py > 0.f ? 1.f : 0.f;
                    float *Sh = S + (0 * MT + p) * SROW + n;
                    float *S0 = S + (1 * MT + p) * SROW + n;
                    float *S1 = S + (2 * MT + p) * SROW + n;
                    Sh[0] = fmaxf(px, 0.f);       Sh[1] = fmaxf(py, 0.f);
                    S0[0] = acc[pi][1][j].x * mx; S0[1] = acc[pi][1][j].y * my;
                    S1[0] = acc[pi][2][j].x * mx; S1[1] = acc[pi][2][j].y * my;
                }
            }
            __syncthreads();
        }

        // ---------------- output layer : 256 -> 2, Jacobian + power series
        {
            const float4 *Wog = reinterpret_cast<const float4 *>(Wo + (size_t)b * HDIM * 2);
            float4 *Wos4 = reinterpret_cast<float4 *>(Wos);
            if (tid < 128) Wos4[tid] = Wog[tid];
        }
        __syncthreads();

        if (tid < 192) {     // 32 points x 3 states x 2 output cols
            int p   = tid & 31;
            int idx = tid >> 5;          // 0..5 = s*2 + c
            int s = idx >> 1, c = idx & 1;
            const float *Sr = S + (s * MT + p) * SROW;
            float sum = 0.f;
            #pragma unroll 8
            for (int k = 0; k < HDIM; ++k)
                sum = fmaf(Sr[k], Wos[2 * k + c], sum);
            red[idx * 32 + p] = sum;
        }
        __syncthreads();

        if (tid < MT) {
            int p = tid;
            float bo0 = __ldg(bo + b * 2 + 0);
            float bo1 = __ldg(bo + b * 2 + 1);
            float pre0 = red[0 * 32 + p] + bo0;     // primal out col 0
            float pre1 = red[1 * 32 + p] + bo1;     // primal out col 1
            float m0 = pre0 > 0.f ? 1.f : 0.f;
            float m1 = pre1 > 0.f ? 1.f : 0.f;
            // J[out][in]; s=1 <-> input dir 0, s=2 <-> input dir 1
            float J00 = red[2 * 32 + p] * m0;   // (s=1,c=0)
            float J10 = red[3 * 32 + p] * m1;   // (s=1,c=1)
            float J01 = red[4 * 32 + p] * m0;   // (s=2,c=0)
            float J11 = red[5 * 32 + p] * m1;   // (s=2,c=1)

            float v0 = vv[2 * p], v1 = vv[2 * p + 1];
            float w0 = v0, w1 = v1;
            float ldet = 0.f;
            const float coefs[5] = {1.f, -0.5f, 1.f / 3.f, -0.25f, 0.2f};
            #pragma unroll
            for (int k = 0; k < 5; ++k) {
                float nw0 = fmaf(J00, w0, J01 * w1);
                float nw1 = fmaf(J10, w0, J11 * w1);
                w0 = nw0; w1 = nw1;
                ldet = fmaf(coefs[k], fmaf(w0, v0, w1 * v1), ldet);
            }
            dl[p] -= ldet;
            zx[2 * p]     += fmaxf(pre0, 0.f);   // z = z + g(z)
            zx[2 * p + 1] += fmaxf(pre1, 0.f);
        }
        __syncthreads();
    }

    if (tid < MT) {
        int g = pbase + tid;
        out[2 * g]     = zx[2 * tid];
        out[2 * g + 1] = zx[2 * tid + 1];
        out[2 * B_PTS + g] = dl[tid];
    }
}

extern "C" void kernel_launch(void *const *d_in, const int *in_sizes, int n_in,
                              void *d_out, int out_size)
{
    const float *x  = (const float *)d_in[0];
    const float *v  = (const float *)d_in[1];
    const float *Wi = (const float *)d_in[2];
    const float *bi = (const float *)d_in[3];
    const float *Wm = (const float *)d_in[4];
    const float *bm = (const float *)d_in[5];
    const float *Wo = (const float *)d_in[6];
    const float *bo = (const float *)d_in[7];
    float *out = (float *)d_out;

    cudaFuncSetAttribute(eq_resflow_kernel,
                         cudaFuncAttributeMaxDynamicSharedMemorySize, SMEM_BYTES);
    eq_resflow_kernel<<<B_PTS / MT, NTHREADS, SMEM_BYTES>>>(x, v, Wi, bi, Wm, bm, Wo, bo, out);
}